// round 15
// baseline (speedup 1.0000x reference)
#include <cuda_runtime.h>
#include <cstddef>

// ---------------------------------------------------------------------------
// ContextNet (RIFE-style) on GB300 — padded buffers.
// conv_a: direct 8co x 4rows (stride 2). conv_b: WINOGRAD F(2x2,3x3) with
// fused splat epilogue. Dual batch pipeline (R13 topology, best proven).
// Levels: (Cin,Cout,Hin): (3,16,512) (16,32,256) (32,64,128) (64,128,64)
// ---------------------------------------------------------------------------

#define NB 16   // total batch
#define NBH 8   // per-pipeline half

__device__ float g_fa[33000000];                       // conv_a outputs (padded)
__device__ float g_fb[33000000];                       // conv_b outputs (padded)
__device__ float g_scrA[(size_t)16 * 16 * 256 * 256];  // channel-last splat scratch (ping)
__device__ float g_scrB[(size_t)16 * 16 * 256 * 256];  // (pong)
__device__ float g_cntA[(size_t)16 * 256 * 256];
__device__ float g_cntB[(size_t)16 * 256 * 256];
__device__ float g_fl[3000000];                        // all 4 halved flows
__device__ float g_wu[360000];                         // Winograd-transformed conv_b weights

// ---- vectorized global reduction (fp32 x4) --------------------------------
__device__ __forceinline__ void red_add_v4(float* p, float a, float b,
                                           float c, float d) {
    asm volatile("red.global.add.v4.f32 [%0], {%1, %2, %3, %4};"
                 :: "l"(p), "f"(a), "f"(b), "f"(c), "f"(d) : "memory");
}

// ---------------------------------------------------------------------------
// Winograd weight transform U = G g G^T for all 4 levels' conv_b weights.
// Pair counts: 256, 1024, 4096, 16384 (cum 256,1280,5376,21760).
// U offsets (floats): 0, 4096, 20480, 86016.
// ---------------------------------------------------------------------------
__global__ void wino_wt_all(const float* __restrict__ w0,
                            const float* __restrict__ w1,
                            const float* __restrict__ w2,
                            const float* __restrict__ w3,
                            float* __restrict__ u) {
    int id = blockIdx.x * 256 + threadIdx.x;
    const float* w; int local; float* up;
    if      (id < 256)   { w = w0; local = id;        up = u;         }
    else if (id < 1280)  { w = w1; local = id - 256;  up = u + 4096;  }
    else if (id < 5376)  { w = w2; local = id - 1280; up = u + 20480; }
    else if (id < 21760) { w = w3; local = id - 5376; up = u + 86016; }
    else return;
    const float* g = w + (size_t)local * 9;
    float gg[4][3];
#pragma unroll
    for (int j = 0; j < 3; j++) {
        gg[0][j] = g[j];
        gg[1][j] = (g[j] + g[3 + j] + g[6 + j]) * 0.5f;
        gg[2][j] = (g[j] - g[3 + j] + g[6 + j]) * 0.5f;
        gg[3][j] = g[6 + j];
    }
    float* U = up + (size_t)local * 16;
#pragma unroll
    for (int i = 0; i < 4; i++) {
        float a0 = gg[i][0], a1 = gg[i][1], a2 = gg[i][2];
        U[i * 4 + 0] = a0;
        U[i * 4 + 1] = (a0 + a1 + a2) * 0.5f;
        U[i * 4 + 2] = (a0 - a1 + a2) * 0.5f;
        U[i * 4 + 3] = a2;
    }
}

// ---------------------------------------------------------------------------
// Merged border zeroing: blockIdx.y selects one of up to 8 jobs.
// ---------------------------------------------------------------------------
struct BorderJobs {
    int    sel[8];    // 0 = fa, 1 = fb
    long long off[8];
    int    NC[8];
    int    H[8];
    int    njobs;
};

__global__ void zero_borders_all(float* __restrict__ fa, float* __restrict__ fb,
                                 BorderJobs J) {
    int j = blockIdx.y;
    if (j >= J.njobs) return;
    int H = J.H[j], NC = J.NC[j];
    int W = H;
    int per = 2 * (W + 2) + 2 * H;
    int idx = blockIdx.x * blockDim.x + threadIdx.x;
    if (idx >= NC * per) return;
    int c = idx / per, r = idx % per;
    float* p = (J.sel[j] ? fb : fa) + J.off[j] + (size_t)c * (H + 2) * (W + 2);
    if (r < W + 2) {
        p[r] = 0.f;
    } else if (r < 2 * (W + 2)) {
        p[(size_t)(H + 1) * (W + 2) + (r - (W + 2))] = 0.f;
    } else {
        int rr = r - 2 * (W + 2);
        int y = rr % H;
        bool right = rr >= H;
        p[(size_t)(y + 1) * (W + 2) + (right ? (W + 1) : 0)] = 0.f;
    }
}

// ---------------------------------------------------------------------------
// Direct 3x3 conv + bias + PReLU (used for conv_a, stride 2, 8co x 4rows).
// ---------------------------------------------------------------------------
template <int STRIDE, int ROWS, int COB, bool PRED, int MINB>
__global__ void __launch_bounds__(256, MINB)
conv3x3_prelu(const float* __restrict__ in,
              const float* __restrict__ wt,
              const float* __restrict__ bias,
              const float* __restrict__ alpha,
              float* __restrict__ out,
              int Cin, int Cout, int Hin, int Win,
              int inPitch, size_t inPlane,
              int outPitch, size_t outPlane,
              int n0) {
    const int cg = Cout / COB;
    const int co0 = (blockIdx.z % cg) * COB;
    const int n   = n0 + blockIdx.z / cg;

    extern __shared__ float sw[];            // [COB][Cin][9]
    const int tid = threadIdx.y * 32 + threadIdx.x;
    const int nw = COB * Cin * 9;
    const float* wsrc = wt + (size_t)co0 * Cin * 9;
    for (int i = tid; i < nw; i += 256) sw[i] = wsrc[i];
    __syncthreads();

    const int x  = blockIdx.x * 32 + threadIdx.x;
    const int y0 = blockIdx.y * (8 * ROWS) + threadIdx.y * ROWS;

    float acc[COB][ROWS];
#pragma unroll
    for (int c = 0; c < COB; c++)
#pragma unroll
        for (int j = 0; j < ROWS; j++) acc[c][j] = 0.f;

    const float* ib = in + (size_t)n * Cin * inPlane;
    constexpr int NR = (STRIDE == 1) ? (ROWS + 2) : (2 * ROWS + 1);

    for (int ci = 0; ci < Cin; ci++) {
        const float* ip = ib + (size_t)ci * inPlane;
        float v[NR][3];
#pragma unroll
        for (int r = 0; r < NR; r++) {
            const int iy = STRIDE * y0 - 1 + r;
            const float* rp = ip + (ptrdiff_t)iy * inPitch + (STRIDE * x - 1);
            if (PRED) {
                bool yok = ((unsigned)iy < (unsigned)Hin);
#pragma unroll
                for (int c = 0; c < 3; c++) {
                    int ix = STRIDE * x - 1 + c;
                    v[r][c] = (yok && (unsigned)ix < (unsigned)Win) ? rp[c] : 0.f;
                }
            } else {
#pragma unroll
                for (int c = 0; c < 3; c++) v[r][c] = rp[c];
            }
        }
#pragma unroll
        for (int c4 = 0; c4 < COB; c4++) {
            const float* w9 = sw + (c4 * Cin + ci) * 9;
            float w[9];
#pragma unroll
            for (int k = 0; k < 9; k++) w[k] = w9[k];
#pragma unroll
            for (int j = 0; j < ROWS; j++)
#pragma unroll
                for (int ky = 0; ky < 3; ky++)
#pragma unroll
                    for (int kx = 0; kx < 3; kx++)
                        acc[c4][j] = fmaf(v[STRIDE * j + ky][kx], w[ky * 3 + kx], acc[c4][j]);
        }
    }

#pragma unroll
    for (int c4 = 0; c4 < COB; c4++) {
        const int co = co0 + c4;
        const float bv = bias[co];
        const float av = alpha[co];
        float* ob = out + (size_t)(n * Cout + co) * outPlane;
#pragma unroll
        for (int j = 0; j < ROWS; j++) {
            float o = acc[c4][j] + bv;
            o = (o >= 0.f) ? o : av * o;
            ob[(size_t)(y0 + j) * outPitch + x] = o;
        }
    }
}

// ---------------------------------------------------------------------------
// Winograd F(2x2,3x3) conv + bias + PReLU + optional writeout + fused splat.
// One 2x2 output tile x 4 co per thread. Input/output padded (pitch, plane).
// uw: transformed weights [Cout][Cin][16].
// ---------------------------------------------------------------------------
template <bool WROUT>
__global__ void __launch_bounds__(256, 2)
winoconv_splat(const float* __restrict__ in,
               const float* __restrict__ uw,
               const float* __restrict__ bias,
               const float* __restrict__ alpha,
               float* __restrict__ out,
               int Cin, int Cout, int W,
               int pitch, size_t plane,
               const float* __restrict__ flw,
               float* __restrict__ scr,
               float* __restrict__ cnt,
               int n0) {
    const int cg = Cout >> 2;
    const int co0 = (blockIdx.z % cg) * 4;
    const int n   = n0 + blockIdx.z / cg;

    extern __shared__ float sw[];            // [4][Cin][16]
    const int tid = threadIdx.x;
    const int nw = 4 * Cin * 16;
    const float* usrc = uw + (size_t)co0 * Cin * 16;
    for (int i = tid; i < nw; i += 256) sw[i] = usrc[i];
    __syncthreads();

    const int TX = W >> 1;
    const int t  = blockIdx.x * 256 + tid;
    const int tX = t % TX, tY = t / TX;
    const int ox = 2 * tX, oy = 2 * tY;

    float acc[4][16];
#pragma unroll
    for (int c = 0; c < 4; c++)
#pragma unroll
        for (int k = 0; k < 16; k++) acc[c][k] = 0.f;

    const float* ib = in + (size_t)n * Cin * plane
                      + (ptrdiff_t)(oy - 1) * pitch + (ox - 1);
    for (int ci = 0; ci < Cin; ci++) {
        const float* ip = ib + (size_t)ci * plane;
        float d[4][4];
#pragma unroll
        for (int r = 0; r < 4; r++)
#pragma unroll
            for (int c = 0; c < 4; c++)
                d[r][c] = ip[(ptrdiff_t)r * pitch + c];

        // B^T d (combine rows)
        float e[4][4];
#pragma unroll
        for (int c = 0; c < 4; c++) {
            e[0][c] = d[0][c] - d[2][c];
            e[1][c] = d[1][c] + d[2][c];
            e[2][c] = d[2][c] - d[1][c];
            e[3][c] = d[1][c] - d[3][c];
        }
        // (B^T d) B (combine cols)
        float D[16];
#pragma unroll
        for (int r = 0; r < 4; r++) {
            D[r * 4 + 0] = e[r][0] - e[r][2];
            D[r * 4 + 1] = e[r][1] + e[r][2];
            D[r * 4 + 2] = e[r][2] - e[r][1];
            D[r * 4 + 3] = e[r][1] - e[r][3];
        }
        // pointwise accumulate (U via LDS.128)
#pragma unroll
        for (int c4 = 0; c4 < 4; c4++) {
            const float4* wp = reinterpret_cast<const float4*>(
                sw + (size_t)(c4 * Cin + ci) * 16);
            float4 u0 = wp[0], u1 = wp[1], u2 = wp[2], u3 = wp[3];
            acc[c4][0]  = fmaf(D[0],  u0.x, acc[c4][0]);
            acc[c4][1]  = fmaf(D[1],  u0.y, acc[c4][1]);
            acc[c4][2]  = fmaf(D[2],  u0.z, acc[c4][2]);
            acc[c4][3]  = fmaf(D[3],  u0.w, acc[c4][3]);
            acc[c4][4]  = fmaf(D[4],  u1.x, acc[c4][4]);
            acc[c4][5]  = fmaf(D[5],  u1.y, acc[c4][5]);
            acc[c4][6]  = fmaf(D[6],  u1.z, acc[c4][6]);
            acc[c4][7]  = fmaf(D[7],  u1.w, acc[c4][7]);
            acc[c4][8]  = fmaf(D[8],  u2.x, acc[c4][8]);
            acc[c4][9]  = fmaf(D[9],  u2.y, acc[c4][9]);
            acc[c4][10] = fmaf(D[10], u2.z, acc[c4][10]);
            acc[c4][11] = fmaf(D[11], u2.w, acc[c4][11]);
            acc[c4][12] = fmaf(D[12], u3.x, acc[c4][12]);
            acc[c4][13] = fmaf(D[13], u3.y, acc[c4][13]);
            acc[c4][14] = fmaf(D[14], u3.z, acc[c4][14]);
            acc[c4][15] = fmaf(D[15], u3.w, acc[c4][15]);
        }
    }

    // inverse transform A^T M A + bias + PReLU -> ypix[pixel][channel]
    float ypix[4][4];
#pragma unroll
    for (int c4 = 0; c4 < 4; c4++) {
        const float bv = bias[co0 + c4];
        const float av = alpha[co0 + c4];
        const float* m = acc[c4];
        float s0[4], s1[4];
#pragma unroll
        for (int c = 0; c < 4; c++) {
            s0[c] = m[c] + m[4 + c] + m[8 + c];
            s1[c] = m[4 + c] - m[8 + c] - m[12 + c];
        }
        float y00 = s0[0] + s0[1] + s0[2];
        float y01 = s0[1] - s0[2] - s0[3];
        float y10 = s1[0] + s1[1] + s1[2];
        float y11 = s1[1] - s1[2] - s1[3];
        y00 += bv; y00 = (y00 >= 0.f) ? y00 : av * y00;
        y01 += bv; y01 = (y01 >= 0.f) ? y01 : av * y01;
        y10 += bv; y10 = (y10 >= 0.f) ? y10 : av * y10;
        y11 += bv; y11 = (y11 >= 0.f) ? y11 : av * y11;
        ypix[0][c4] = y00; ypix[1][c4] = y01;
        ypix[2][c4] = y10; ypix[3][c4] = y11;
    }

    if (WROUT) {
#pragma unroll
        for (int c4 = 0; c4 < 4; c4++) {
            float* ob = out + (size_t)(n * Cout + co0 + c4) * plane;
            ob[(size_t)oy * pitch + ox]           = ypix[0][c4];
            ob[(size_t)oy * pitch + ox + 1]       = ypix[1][c4];
            ob[(size_t)(oy + 1) * pitch + ox]     = ypix[2][c4];
            ob[(size_t)(oy + 1) * pitch + ox + 1] = ypix[3][c4];
        }
    }

    // fused forward splat of the 2x2 pixels
    {
        const int HW = W * W;
        const float* fp = flw + (size_t)n * 2 * HW;
        float* sb = scr + (size_t)n * HW * Cout + co0;
#pragma unroll
        for (int p = 0; p < 4; p++) {
            const int xx = ox + (p & 1);
            const int yy = oy + (p >> 1);
            const int pq = yy * W + xx;
            float fx = fp[pq] + (float)xx;
            float fy = fp[HW + pq] + (float)yy;
            float x0f = floorf(fx), y0f = floorf(fy);
            int ix0 = (int)x0f, iy0 = (int)y0f;
            float wx1 = fx - x0f, wy1 = fy - y0f;
            float wx0 = 1.f - wx1, wy0 = 1.f - wy1;
            int   xi[4] = {ix0, ix0 + 1, ix0,     ix0 + 1};
            int   yi[4] = {iy0, iy0,     iy0 + 1, iy0 + 1};
            float wv[4] = {wx0 * wy0, wx1 * wy0, wx0 * wy1, wx1 * wy1};
            float s0 = ypix[p][0], s1 = ypix[p][1];
            float s2 = ypix[p][2], s3 = ypix[p][3];
#pragma unroll
            for (int k = 0; k < 4; k++) {
                bool ok = ((unsigned)xi[k] < (unsigned)W) &&
                          ((unsigned)yi[k] < (unsigned)W);
                if (ok) {
                    int tgt = yi[k] * W + xi[k];
                    float w = wv[k];
                    red_add_v4(sb + (size_t)tgt * Cout,
                               s0 * w, s1 * w, s2 * w, s3 * w);
                    if (co0 == 0)
                        atomicAdd(&cnt[(size_t)n * HW + tgt], w);
                }
            }
        }
    }
}

// ---------------------------------------------------------------------------
// Flow halving: 2x2 mean * 0.5 == sum * 0.125
// ---------------------------------------------------------------------------
__global__ void halve_flow_kernel(const float* __restrict__ in,
                                  float* __restrict__ out, int Hout, int Wout) {
    int idx = blockIdx.x * blockDim.x + threadIdx.x;
    int total = NB * 2 * Hout * Wout;
    if (idx >= total) return;
    int w = idx % Wout;
    int h = (idx / Wout) % Hout;
    int nc = idx / (Wout * Hout);
    int Win = 2 * Wout;
    const float* ip = in + (size_t)nc * (4 * Hout * Wout);
    const float* r0 = ip + (2 * h) * Win + 2 * w;
    const float* r1 = r0 + Win;
    out[idx] = (r0[0] + r0[1] + r1[0] + r1[1]) * 0.125f;
}

// ---------------------------------------------------------------------------
// Transpose channel-last scratch [n][p][c] -> NCHW out, dividing by count.
// ---------------------------------------------------------------------------
__global__ void norm_transpose(const float* __restrict__ scr,
                               const float* __restrict__ cnt,
                               float* __restrict__ out,
                               int C, int HW) {
    __shared__ float tile[32][33];
    const int n  = blockIdx.z;
    const int p0 = blockIdx.x * 32;
    const int c0 = blockIdx.y * 32;
    const int tx = threadIdx.x, ty = threadIdx.y;

    const float* sb = scr + (size_t)n * HW * C;
    const int c = c0 + tx;
#pragma unroll
    for (int r = 0; r < 4; r++) {
        int pl = ty + 8 * r;
        if (c < C)
            tile[pl][tx] = sb[(size_t)(p0 + pl) * C + c];
    }
    __syncthreads();

    float cv = cnt[(size_t)n * HW + p0 + tx];
    float inv = 1.f / ((cv == 0.f) ? 1.f : cv);
#pragma unroll
    for (int r = 0; r < 4; r++) {
        int cc = c0 + ty + 8 * r;
        if (cc < C)
            out[((size_t)n * C + cc) * HW + p0 + tx] = tile[tx][ty + 8 * r] * inv;
    }
}

// ---------------------------------------------------------------------------
// Host launcher — dual batch pipeline + side stream (graph-capturable).
// ---------------------------------------------------------------------------
extern "C" void kernel_launch(void* const* d_in, const int* in_sizes, int n_in,
                              void* d_out, int out_size) {
    const float* img  = (const float*)d_in[0];
    const float* flow = (const float*)d_in[1];
    float* out = (float*)d_out;

    static cudaStream_t s2 = nullptr, s3 = nullptr;
    static cudaEvent_t evFork, evJoin, evPre[4], evB0[4], evB1[4];
    if (!s2) {
        cudaStreamCreateWithFlags(&s2, cudaStreamNonBlocking);
        cudaStreamCreateWithFlags(&s3, cudaStreamNonBlocking);
        cudaEventCreateWithFlags(&evFork, cudaEventDisableTiming);
        cudaEventCreateWithFlags(&evJoin, cudaEventDisableTiming);
        for (int i = 0; i < 4; i++) {
            cudaEventCreateWithFlags(&evPre[i], cudaEventDisableTiming);
            cudaEventCreateWithFlags(&evB0[i], cudaEventDisableTiming);
            cudaEventCreateWithFlags(&evB1[i], cudaEventDisableTiming);
        }
    }

    float *fa, *fb, *scrA, *scrB, *cntA, *cntB, *flbuf, *wu;
    cudaGetSymbolAddress((void**)&fa,   g_fa);
    cudaGetSymbolAddress((void**)&fb,   g_fb);
    cudaGetSymbolAddress((void**)&scrA, g_scrA);
    cudaGetSymbolAddress((void**)&scrB, g_scrB);
    cudaGetSymbolAddress((void**)&cntA, g_cntA);
    cudaGetSymbolAddress((void**)&cntB, g_cntB);
    cudaGetSymbolAddress((void**)&flbuf, g_fl);
    cudaGetSymbolAddress((void**)&wu,   g_wu);

    const int Cin[4]  = {3, 16, 32, 64};
    const int Cout[4] = {16, 32, 64, 128};
    const int Hin[4]  = {512, 256, 128, 64};
    const size_t uOff[4] = {0, 4096, 20480, 86016};

    size_t regOff[4];
    float* fl[4];
    {
        size_t a = 0, f = 0;
        for (int L = 0; L < 4; L++) {
            regOff[L] = a;
            int ho = Hin[L] / 2;
            a += (size_t)NB * Cout[L] * (ho + 2) * (ho + 2);
            fl[L] = flbuf + f;
            f += (size_t)NB * 2 * ho * ho;
        }
    }
    float* scrP[4] = {scrA, scrB, scrA, scrB};
    float* cntP[4] = {cntA, cntB, cntA, cntB};

    // ---- fork ----
    cudaEventRecord(evFork, 0);
    cudaStreamWaitEvent(s2, evFork, 0);
    cudaStreamWaitEvent(s3, evFork, 0);

    // ---- side stream: Winograd weight transform first ----
    wino_wt_all<<<85, 256, 0, s2>>>(
        (const float*)d_in[2 + 3], (const float*)d_in[8 + 3],
        (const float*)d_in[14 + 3], (const float*)d_in[20 + 3], wu);

    // ---- side stream: borders (merged), flow chain, first memsets ----
    {
        BorderJobs J{};
        int nj = 0;
        int maxtot = 0;
        for (int L = 0; L < 4; L++) {
            int ho = Hin[L] / 2;
            J.sel[nj] = 0; J.off[nj] = (long long)regOff[L];
            J.NC[nj] = NB * Cout[L]; J.H[nj] = ho;
            int tot = J.NC[nj] * (2 * (ho + 2) + 2 * ho);
            if (tot > maxtot) maxtot = tot;
            nj++;
            if (L < 3) {
                J.sel[nj] = 1; J.off[nj] = (long long)regOff[L];
                J.NC[nj] = NB * Cout[L]; J.H[nj] = ho;
                nj++;
            }
        }
        J.njobs = nj;
        dim3 grd((maxtot + 255) / 256, nj);
        zero_borders_all<<<grd, 256, 0, s2>>>(fa, fb, J);
    }

    {
        int ho0 = Hin[0] / 2;
        halve_flow_kernel<<<(NB * 2 * ho0 * ho0 + 255) / 256, 256, 0, s2>>>(
            flow, fl[0], ho0, ho0);
        cudaMemsetAsync(scrP[0], 0, (size_t)NB * Cout[0] * ho0 * ho0 * sizeof(float), s2);
        cudaMemsetAsync(cntP[0], 0, (size_t)NB * ho0 * ho0 * sizeof(float), s2);
        cudaEventRecord(evPre[0], s2);

        for (int L = 1; L < 4; L++) {
            int ho = Hin[L] / 2;
            halve_flow_kernel<<<(NB * 2 * ho * ho + 255) / 256, 256, 0, s2>>>(
                fl[L - 1], fl[L], ho, ho);
        }
        int ho1 = Hin[1] / 2;
        cudaMemsetAsync(scrP[1], 0, (size_t)NB * Cout[1] * ho1 * ho1 * sizeof(float), s2);
        cudaMemsetAsync(cntP[1], 0, (size_t)NB * ho1 * ho1 * sizeof(float), s2);
        cudaEventRecord(evPre[1], s2);
    }

    size_t off = 0;
    size_t outOff[4];
    for (int L = 0; L < 4; L++) { outOff[L] = off; off += (size_t)NB * Cout[L] * (Hin[L] / 2) * (Hin[L] / 2); }

    cudaStream_t hs[2] = {(cudaStream_t)0, s3};
    cudaEvent_t* evBh[2] = {evB0, evB1};

    for (int L = 0; L < 4; L++) {
        const int ci = Cin[L], co = Cout[L], hi = Hin[L], ho = hi / 2;
        const float* wA = (const float*)d_in[2 + 6 * L + 0];
        const float* bA = (const float*)d_in[2 + 6 * L + 1];
        const float* aA = (const float*)d_in[2 + 6 * L + 2];
        const float* bB = (const float*)d_in[2 + 6 * L + 4];
        const float* aB = (const float*)d_in[2 + 6 * L + 5];

        const int po = ho + 2;
        const size_t planeO = (size_t)po * po;
        float* faL = fa + regOff[L] + po + 1;
        float* fbL = fb + regOff[L] + po + 1;

        for (int h = 0; h < 2; h++) {
            cudaStream_t st = hs[h];
            const int n0 = h * NBH;

            // --- conv_a: direct stride 2, 8co x 4rows ---
            {
                dim3 blk(32, 8);
                dim3 grd(ho / 32, ho / 32, NBH * (co / 8));
                size_t sm = 8 * ci * 9 * sizeof(float);
                if (L == 0) {
                    conv3x3_prelu<2, 4, 8, true, 2><<<grd, blk, sm, st>>>(
                        img, wA, bA, aA, faL, ci, co, hi, hi,
                        hi, (size_t)hi * hi, po, planeO, n0);
                } else {
                    const int pi = hi + 2;
                    const float* inL = fb + regOff[L - 1] + pi + 1;
                    conv3x3_prelu<2, 4, 8, false, 2><<<grd, blk, sm, st>>>(
                        inL, wA, bA, aA, faL, ci, co, hi, hi,
                        pi, (size_t)pi * pi, po, planeO, n0);
                }
            }

            cudaStreamWaitEvent(st, evPre[L], 0);

            // --- conv_b: Winograd F(2x2,3x3) + fused splat; no fb write at L3 ---
            {
                const int TX = ho / 2;
                dim3 blk(256, 1, 1);
                dim3 grd((TX * TX) / 256, 1, NBH * (co / 4));
                size_t sm = 4 * co * 16 * sizeof(float);
                if (L < 3) {
                    winoconv_splat<true><<<grd, blk, sm, st>>>(
                        faL, wu + uOff[L], bB, aB, fbL, co, co, ho,
                        po, planeO, fl[L], scrP[L], cntP[L], n0);
                } else {
                    winoconv_splat<false><<<grd, blk, sm, st>>>(
                        faL, wu + uOff[L], bB, aB, fbL, co, co, ho,
                        po, planeO, fl[L], scrP[L], cntP[L], n0);
                }
            }
            cudaEventRecord(evBh[h][L], st);
        }

        // --- side stream: transpose this level after BOTH halves; memset L+2 ---
        cudaStreamWaitEvent(s2, evB0[L], 0);
        cudaStreamWaitEvent(s2, evB1[L], 0);
        {
            int HW = ho * ho;
            dim3 blk(32, 8);
            dim3 grd(HW / 32, (co + 31) / 32, NB);
            norm_transpose<<<grd, blk, 0, s2>>>(scrP[L], cntP[L], out + outOff[L], co, HW);
        }
        if (L + 2 < 4) {
            int ho2 = Hin[L + 2] / 2;
            cudaMemsetAsync(scrP[L + 2], 0,
                            (size_t)NB * Cout[L + 2] * ho2 * ho2 * sizeof(float), s2);
            cudaMemsetAsync(cntP[L + 2], 0,
                            (size_t)NB * ho2 * ho2 * sizeof(float), s2);
            cudaEventRecord(evPre[L + 2], s2);
        }
    }

    // ---- join ----
    cudaEventRecord(evJoin, s2);
    cudaStreamWaitEvent(0, evJoin, 0);
}